// round 2
// baseline (speedup 1.0000x reference)
#include <cuda_runtime.h>
#include <math.h>

#define DIM 128
#define NITER 8

// Static scratch (allocation-free rule: __device__ globals)
#define MAXL 100096ull
#define MAXC 150016ull
#define MAXN 150016ull
#define MAXE 450048

__device__ float g_hid  [MAXN * 128];   // MLP hidden
__device__ float g_lfeat[MAXL * 128];   // l2c message features per literal
__device__ float g_cfeat[MAXC * 128];   // c2l message features per clause
__device__ float g_caggr[MAXC * 128];   // segment-sum into clauses
__device__ float g_lx   [MAXL * 256];   // [c2l_aggr | l2l_msg] concat, lGRU input
__device__ float g_gi   [MAXN * 384];   // GRU input gates
__device__ float g_gh   [MAXN * 384];   // GRU hidden gates
__device__ int   g_lei32[MAXE];
__device__ int   g_cei32[MAXE];
__device__ int   g_is64;

// ---------------------------------------------------------------------------
// Edge-index dtype detection + normalization to int32.
// jnp.int64 under default JAX config silently produces int32; handle both.
// ---------------------------------------------------------------------------
__global__ void detect_idx64(const unsigned int* __restrict__ a,
                             const unsigned int* __restrict__ b, int E)
{
    int n = E < 32 ? E : 32;
    int is64 = 1;
    for (int i = 0; i < n; i++) {
        if (a[2 * i + 1] != 0u) is64 = 0;   // high word of would-be int64
        if (b[2 * i + 1] != 0u) is64 = 0;
    }
    g_is64 = is64;
}

__global__ void convert_idx(const void* __restrict__ srcA,
                            const void* __restrict__ srcB,
                            int* __restrict__ dstA,
                            int* __restrict__ dstB, int E)
{
    int e = blockIdx.x * blockDim.x + threadIdx.x;
    if (e >= E) return;
    if (g_is64) {
        dstA[e] = (int)((const long long*)srcA)[e];
        dstB[e] = (int)((const long long*)srcB)[e];
    } else {
        dstA[e] = ((const int*)srcA)[e];
        dstB[e] = ((const int*)srcB)[e];
    }
}

// ---------------------------------------------------------------------------
// Tiled fp32 GEMM:  Y[N,M] = act( X[N,K] @ W[M,K]^T + b )
// Both X and W are K-contiguous (NT / dot-of-rows). BM=BN=64, BK=32,
// 256 threads, 4x4 microtile per thread, float4 smem reads.
// XORROW: A row index r reads row (r^1)  (literal polarity flip).
// ---------------------------------------------------------------------------
template<bool RELU, bool XORROW>
__global__ __launch_bounds__(256)
void gemm_nt(const float* __restrict__ A, int lda,
             const float* __restrict__ W,
             const float* __restrict__ bias,
             float* __restrict__ Cmat, int ldc, int ccol,
             int N, int M, int K)
{
    __shared__ float Xs[32][64];
    __shared__ float Ws[32][64];

    const int bm = blockIdx.x * 64;
    const int bn = blockIdx.y * 64;
    const int tid = threadIdx.x;
    const int tx = tid & 15;        // col group
    const int ty = tid >> 4;        // row group

    float acc[4][4] = {};

    for (int k0 = 0; k0 < K; k0 += 32) {
        #pragma unroll
        for (int t = 0; t < 2; t++) {
            int i   = tid + t * 256;       // 0..511
            int row = i >> 3;              // 0..63
            int kk  = (i & 7) << 2;        // 0,4,...,28

            int grow = bm + row;
            float4 v = make_float4(0.f, 0.f, 0.f, 0.f);
            if (grow < N) {
                int srow = XORROW ? (grow ^ 1) : grow;
                v = *(const float4*)(A + (size_t)srow * lda + k0 + kk);
            }
            Xs[kk + 0][row] = v.x; Xs[kk + 1][row] = v.y;
            Xs[kk + 2][row] = v.z; Xs[kk + 3][row] = v.w;

            float4 w = *(const float4*)(W + (size_t)(bn + row) * K + k0 + kk);
            Ws[kk + 0][row] = w.x; Ws[kk + 1][row] = w.y;
            Ws[kk + 2][row] = w.z; Ws[kk + 3][row] = w.w;
        }
        __syncthreads();

        #pragma unroll
        for (int kk = 0; kk < 32; kk++) {
            float4 xv = *(const float4*)&Xs[kk][ty << 2];
            float4 wv = *(const float4*)&Ws[kk][tx << 2];
            float xr[4] = {xv.x, xv.y, xv.z, xv.w};
            float wr[4] = {wv.x, wv.y, wv.z, wv.w};
            #pragma unroll
            for (int i = 0; i < 4; i++)
                #pragma unroll
                for (int j = 0; j < 4; j++)
                    acc[i][j] += xr[i] * wr[j];
        }
        __syncthreads();
    }

    float4 bv = *(const float4*)(bias + bn + (tx << 2));
    float br[4] = {bv.x, bv.y, bv.z, bv.w};

    #pragma unroll
    for (int i = 0; i < 4; i++) {
        int row = bm + (ty << 2) + i;
        if (row < N) {
            float4 o;
            o.x = acc[i][0] + br[0];
            o.y = acc[i][1] + br[1];
            o.z = acc[i][2] + br[2];
            o.w = acc[i][3] + br[3];
            if (RELU) {
                o.x = fmaxf(o.x, 0.f); o.y = fmaxf(o.y, 0.f);
                o.z = fmaxf(o.z, 0.f); o.w = fmaxf(o.w, 0.f);
            }
            *(float4*)(Cmat + (size_t)row * ldc + ccol + bn + (tx << 2)) = o;
        }
    }
}

// ---------------------------------------------------------------------------
// Fused gather + segment-sum:  aggr[dst[e]] += feat[src[e]]   (128 floats/edge)
// One (edge, 4-float chunk) per thread.
// ---------------------------------------------------------------------------
__global__ void edge_aggr(const int* __restrict__ src,
                          const int* __restrict__ dst,
                          const float* __restrict__ feat,
                          float* __restrict__ aggr, int ldc, int E,
                          int maxS, int maxD)
{
    long long idx = (long long)blockIdx.x * blockDim.x + threadIdx.x;
    int e = (int)(idx >> 5);
    if (e >= E) return;
    int c = (int)(idx & 31) << 2;

    int s = src[e];
    int d = dst[e];
    if ((unsigned)s >= (unsigned)maxS || (unsigned)d >= (unsigned)maxD) return;
    float4 v = *(const float4*)(feat + (size_t)s * 128 + c);
    float* p = aggr + (size_t)d * ldc + c;
    atomicAdd(p + 0, v.x);
    atomicAdd(p + 1, v.y);
    atomicAdd(p + 2, v.z);
    atomicAdd(p + 3, v.w);
}

// ---------------------------------------------------------------------------
// GRU pointwise: h' = (1-z)*n + z*h  with r,z,n from gi/gh [N,384]
// (biases already folded into gi/gh by the GEMMs)
// ---------------------------------------------------------------------------
__global__ void gru_pointwise(const float* __restrict__ gi,
                              const float* __restrict__ gh,
                              const float* __restrict__ h,
                              float* __restrict__ hout, int N)
{
    long long idx = (long long)blockIdx.x * blockDim.x + threadIdx.x;
    if (idx >= (long long)N * 128) return;
    int n = (int)(idx >> 7);
    int j = (int)(idx & 127);

    const float* gip = gi + (size_t)n * 384;
    const float* ghp = gh + (size_t)n * 384;

    float r = 1.f / (1.f + expf(-(gip[j]       + ghp[j])));
    float z = 1.f / (1.f + expf(-(gip[128 + j] + ghp[128 + j])));
    float nn = tanhf(gip[256 + j] + r * ghp[256 + j]);
    hout[idx] = (1.f - z) * nn + z * h[idx];
}

// ---------------------------------------------------------------------------
static void gemm(const float* A, int lda, const float* W, const float* b,
                 float* Cm, int ldc, int ccol, int N, int M, int K,
                 bool relu, bool xorrow)
{
    dim3 grid((N + 63) / 64, M / 64);
    if (relu) {
        if (xorrow) gemm_nt<true,  true ><<<grid, 256>>>(A, lda, W, b, Cm, ldc, ccol, N, M, K);
        else        gemm_nt<true,  false><<<grid, 256>>>(A, lda, W, b, Cm, ldc, ccol, N, M, K);
    } else {
        gemm_nt<false, false><<<grid, 256>>>(A, lda, W, b, Cm, ldc, ccol, N, M, K);
    }
}

extern "C" void kernel_launch(void* const* d_in, const int* in_sizes, int n_in,
                              void* d_out, int out_size)
{
    // setup_inputs may or may not surface the two python-int scalars as inputs
    int base = (n_in >= 26) ? 2 : 0;

    const void*  l_ei_raw = d_in[base + 0];
    const void*  c_ei_raw = d_in[base + 1];
    const float* l_emb0   = (const float*)d_in[base + 2];
    const float* c_emb0   = (const float*)d_in[base + 3];

    const float* l2c_W1 = (const float*)d_in[base + 4];
    const float* l2c_b1 = (const float*)d_in[base + 5];
    const float* l2c_W2 = (const float*)d_in[base + 6];
    const float* l2c_b2 = (const float*)d_in[base + 7];
    const float* c2l_W1 = (const float*)d_in[base + 8];
    const float* c2l_b1 = (const float*)d_in[base + 9];
    const float* c2l_W2 = (const float*)d_in[base + 10];
    const float* c2l_b2 = (const float*)d_in[base + 11];
    const float* l2l_W1 = (const float*)d_in[base + 12];
    const float* l2l_b1 = (const float*)d_in[base + 13];
    const float* l2l_W2 = (const float*)d_in[base + 14];
    const float* l2l_b2 = (const float*)d_in[base + 15];
    const float* cgru_Wih = (const float*)d_in[base + 16];
    const float* cgru_Whh = (const float*)d_in[base + 17];
    const float* cgru_bih = (const float*)d_in[base + 18];
    const float* cgru_bhh = (const float*)d_in[base + 19];
    const float* lgru_Wih = (const float*)d_in[base + 20];
    const float* lgru_Whh = (const float*)d_in[base + 21];
    const float* lgru_bih = (const float*)d_in[base + 22];
    const float* lgru_bhh = (const float*)d_in[base + 23];

    const int E = in_sizes[base + 0];
    const int L = in_sizes[base + 2] / DIM;
    const int C = in_sizes[base + 3] / DIM;

    float* out   = (float*)d_out;
    float* l_out = out;                                       // [9, L, 128]
    float* c_out = out + (size_t)(NITER + 1) * L * DIM;       // [9, C, 128]

    float *hid, *lfeat, *cfeat, *caggr, *lx, *gi, *gh;
    int *lei, *cei;
    cudaGetSymbolAddress((void**)&hid,   g_hid);
    cudaGetSymbolAddress((void**)&lfeat, g_lfeat);
    cudaGetSymbolAddress((void**)&cfeat, g_cfeat);
    cudaGetSymbolAddress((void**)&caggr, g_caggr);
    cudaGetSymbolAddress((void**)&lx,    g_lx);
    cudaGetSymbolAddress((void**)&gi,    g_gi);
    cudaGetSymbolAddress((void**)&gh,    g_gh);
    cudaGetSymbolAddress((void**)&lei,   g_lei32);
    cudaGetSymbolAddress((void**)&cei,   g_cei32);

    // normalize edge indices (int64 or int32 -> int32)
    detect_idx64<<<1, 1>>>((const unsigned int*)l_ei_raw,
                           (const unsigned int*)c_ei_raw, E);
    convert_idx<<<(E + 255) / 256, 256>>>(l_ei_raw, c_ei_raw, lei, cei, E);

    // slot 0 = initial embeddings
    cudaMemcpyAsync(l_out, l_emb0, (size_t)L * DIM * sizeof(float),
                    cudaMemcpyDeviceToDevice, 0);
    cudaMemcpyAsync(c_out, c_emb0, (size_t)C * DIM * sizeof(float),
                    cudaMemcpyDeviceToDevice, 0);

    const int edge_blocks = (int)(((long long)E * 32 + 255) / 256);

    for (int it = 0; it < NITER; it++) {
        const float* lcur = l_out + (size_t)it * L * DIM;
        const float* ccur = c_out + (size_t)it * C * DIM;
        float* lnext = l_out + (size_t)(it + 1) * L * DIM;
        float* cnext = c_out + (size_t)(it + 1) * C * DIM;

        // --- l2c MLP: lfeat = MLP(l_emb) ---
        gemm(lcur, DIM, l2c_W1, l2c_b1, hid,   DIM, 0, L, DIM, DIM, true,  false);
        gemm(hid,  DIM, l2c_W2, l2c_b2, lfeat, DIM, 0, L, DIM, DIM, false, false);

        // --- c2l MLP: cfeat = MLP(c_emb) ---
        gemm(ccur, DIM, c2l_W1, c2l_b1, hid,   DIM, 0, C, DIM, DIM, true,  false);
        gemm(hid,  DIM, c2l_W2, c2l_b2, cfeat, DIM, 0, C, DIM, DIM, false, false);

        // --- l2l MLP on polarity-flipped rows, into lx cols [128..255] ---
        cudaMemsetAsync(lx, 0, (size_t)L * 256 * sizeof(float), 0);
        gemm(lcur, DIM, l2l_W1, l2l_b1, hid, DIM, 0,   L, DIM, DIM, true,  true);
        gemm(hid,  DIM, l2l_W2, l2l_b2, lx,  256, 128, L, DIM, DIM, false, false);

        // --- fused gather + segment sums ---
        cudaMemsetAsync(caggr, 0, (size_t)C * DIM * sizeof(float), 0);
        edge_aggr<<<edge_blocks, 256>>>(lei, cei, lfeat, caggr, 128, E, L, C);
        edge_aggr<<<edge_blocks, 256>>>(cei, lei, cfeat, lx,    256, E, C, L);

        // --- clause GRU ---
        gemm(caggr, DIM, cgru_Wih, cgru_bih, gi, 384, 0, C, 384, DIM, false, false);
        gemm(ccur,  DIM, cgru_Whh, cgru_bhh, gh, 384, 0, C, 384, DIM, false, false);
        {
            long long tot = (long long)C * 128;
            gru_pointwise<<<(int)((tot + 255) / 256), 256>>>(gi, gh, ccur, cnext, C);
        }

        // --- literal GRU (input = [c2l_aggr | l2l_msg], K=256) ---
        gemm(lx,   256, lgru_Wih, lgru_bih, gi, 384, 0, L, 384, 256, false, false);
        gemm(lcur, DIM, lgru_Whh, lgru_bhh, gh, 384, 0, L, 384, DIM, false, false);
        {
            long long tot = (long long)L * 128;
            gru_pointwise<<<(int)((tot + 255) / 256), 256>>>(gi, gh, lcur, lnext, L);
        }
    }
}

// round 4
// speedup vs baseline: 2.3167x; 2.3167x over previous
#include <cuda_runtime.h>
#include <cuda_bf16.h>
#include <math.h>
#include <stdint.h>

#define DIM 128
#define NITER 8

#define MAXL 100096ull
#define MAXC 150016ull
#define MAXN 150016ull
#define MAXE 450048

// ---------------- fp32 scratch ----------------
__device__ float g_lfeat[MAXL * 128];
__device__ float g_cfeat[MAXC * 128];
__device__ float g_caggr[MAXC * 128];
__device__ float g_lx   [MAXL * 256];
__device__ float g_gi   [MAXN * 384];
__device__ float g_gh   [MAXN * 384];
__device__ int   g_lei32[MAXE];
__device__ int   g_cei32[MAXE];
__device__ int   g_is64;

// ---------------- bf16 split scratch (hi/lo) ----------------
__device__ __nv_bfloat16 g_lcur_h[MAXL * 128], g_lcur_l[MAXL * 128];
__device__ __nv_bfloat16 g_ccur_h[MAXC * 128], g_ccur_l[MAXC * 128];
__device__ __nv_bfloat16 g_hid_h [MAXN * 128], g_hid_l [MAXN * 128];
__device__ __nv_bfloat16 g_cag_h [MAXC * 128], g_cag_l [MAXC * 128];
__device__ __nv_bfloat16 g_lxs_h [MAXL * 256], g_lxs_l [MAXL * 256];
#define WPOOL 344064
__device__ __nv_bfloat16 g_w_h[WPOOL], g_w_l[WPOOL];

// =================== low-level helpers ===================
__device__ __forceinline__ uint32_t smem_to_u32(const void* p) {
    uint32_t a;
    asm("{ .reg .u64 t; cvta.to.shared.u64 t, %1; cvt.u32.u64 %0, t; }"
        : "=r"(a) : "l"(p));
    return a;
}

__device__ __forceinline__ void cp16(uint32_t dst, const void* src, int sz) {
    asm volatile("cp.async.cg.shared.global [%0], [%1], 16, %2;"
                 :: "r"(dst), "l"(src), "r"(sz));
}
#define CP_COMMIT() asm volatile("cp.async.commit_group;" ::: "memory")

__device__ __forceinline__ void ldx4(uint32_t* r, uint32_t addr) {
    asm volatile("ldmatrix.sync.aligned.m8n8.x4.shared.b16 {%0,%1,%2,%3}, [%4];"
                 : "=r"(r[0]), "=r"(r[1]), "=r"(r[2]), "=r"(r[3]) : "r"(addr));
}
__device__ __forceinline__ void ldx2(uint32_t* r, uint32_t addr) {
    asm volatile("ldmatrix.sync.aligned.m8n8.x2.shared.b16 {%0,%1}, [%2];"
                 : "=r"(r[0]), "=r"(r[1]) : "r"(addr));
}
__device__ __forceinline__ void mma_bf16(float* d, const uint32_t* a, const uint32_t* b) {
    asm volatile("mma.sync.aligned.m16n8k16.row.col.f32.bf16.bf16.f32 "
                 "{%0,%1,%2,%3}, {%4,%5,%6,%7}, {%8,%9}, {%0,%1,%2,%3};"
                 : "+f"(d[0]), "+f"(d[1]), "+f"(d[2]), "+f"(d[3])
                 : "r"(a[0]), "r"(a[1]), "r"(a[2]), "r"(a[3]), "r"(b[0]), "r"(b[1]));
}

// smem stage geometry: 4 matrices of 128 rows x 72 bf16 (144B stride)
#define MAT_BYTES 18432          // 128 * 144
#define STAGE_BYTES 73728        // 4 * MAT_BYTES
#define SMEM_BYTES 147456        // 2 stages

// =================== split-bf16 GEMM via mma.sync ===================
// Y[N, M] = act( (Ah+Al)[N,K] @ (Wh+Wl)[M,K]^T + bias )
// grid = (ceil(N/128), M/128), 256 threads (8 warps, 2x4 of 64x32 tiles)
template<int RELU, int XORROW, int SPLITOUT>
__global__ __launch_bounds__(256)
void mma_gemm(const __nv_bfloat16* __restrict__ Ah, const __nv_bfloat16* __restrict__ Al,
              const __nv_bfloat16* __restrict__ Wh, const __nv_bfloat16* __restrict__ Wl,
              const float* __restrict__ bias,
              float* __restrict__ Cf,
              __nv_bfloat16* __restrict__ Ch, __nv_bfloat16* __restrict__ Cl,
              int ldc, int ccol, int N, int M, int K)
{
    extern __shared__ char smem[];
    const uint32_t sb = smem_to_u32(smem);
    const int tid  = threadIdx.x;
    const int lane = tid & 31;
    const int wid  = tid >> 5;
    const int wm   = wid >> 2;          // 0..1
    const int wn   = wid & 3;           // 0..3
    const int bm   = blockIdx.x * 128;
    const int bn   = blockIdx.y * 128;
    const int nchunk = K >> 6;

    float acc[4][4][4] = {};

    // ---- stage loader (cp.async) ----
    auto load_stage = [&](int kc) {
        const uint32_t s0 = sb + (uint32_t)(kc & 1) * STAGE_BYTES;
        const int k0 = kc << 6;
        #pragma unroll
        for (int t = 0; t < 4; t++) {
            int q   = tid + (t << 8);    // 0..1023
            int row = q >> 3;            // 0..127
            int c16 = q & 7;             // 16B unit within 128B row
            uint32_t dS = s0 + (uint32_t)row * 144 + (c16 << 4);

            int grow = bm + row;
            int ok   = grow < N;
            int sr   = ok ? (XORROW ? (grow ^ 1) : grow) : 0;
            int sz   = ok ? 16 : 0;
            const char* pah = (const char*)(Ah + (size_t)sr * K + k0) + (c16 << 4);
            const char* pal = (const char*)(Al + (size_t)sr * K + k0) + (c16 << 4);
            cp16(dS,             pah, sz);
            cp16(dS + MAT_BYTES, pal, sz);

            int brow = bn + row;
            const char* pbh = (const char*)(Wh + (size_t)brow * K + k0) + (c16 << 4);
            const char* pbl = (const char*)(Wl + (size_t)brow * K + k0) + (c16 << 4);
            cp16(dS + 2 * MAT_BYTES, pbh, 16);
            cp16(dS + 3 * MAT_BYTES, pbl, 16);
        }
    };

    load_stage(0);
    CP_COMMIT();

    for (int kc = 0; kc < nchunk; kc++) {
        if (kc + 1 < nchunk) {
            load_stage(kc + 1);
            CP_COMMIT();
            asm volatile("cp.async.wait_group 1;" ::: "memory");
        } else {
            asm volatile("cp.async.wait_group 0;" ::: "memory");
        }
        __syncthreads();

        const uint32_t s0 = sb + (uint32_t)(kc & 1) * STAGE_BYTES;
        // ldmatrix base addresses
        const uint32_t aBase = s0 + (uint32_t)(wm * 64 + (lane & 15)) * 144 + ((lane >> 4) << 4);
        const uint32_t bBase = s0 + 2 * MAT_BYTES
                             + (uint32_t)(wn * 32 + (lane & 7)) * 144 + (((lane >> 3) & 1) << 4);

        #pragma unroll
        for (int k16 = 0; k16 < 4; k16++) {
            const uint32_t kb = k16 << 5;   // 16 bf16 = 32 bytes
            uint32_t ah[4][4], al[4][4];
            #pragma unroll
            for (int mi = 0; mi < 4; mi++) {
                ldx4(ah[mi], aBase + mi * (16 * 144) + kb);
                ldx4(al[mi], aBase + MAT_BYTES + mi * (16 * 144) + kb);
            }
            #pragma unroll
            for (int ni = 0; ni < 4; ni++) {
                uint32_t bh[2], bl[2];
                ldx2(bh, bBase + ni * (8 * 144) + kb);
                ldx2(bl, bBase + MAT_BYTES + ni * (8 * 144) + kb);
                #pragma unroll
                for (int mi = 0; mi < 4; mi++) {
                    mma_bf16(acc[mi][ni], ah[mi], bh);
                    mma_bf16(acc[mi][ni], al[mi], bh);
                    mma_bf16(acc[mi][ni], ah[mi], bl);
                }
            }
        }
        __syncthreads();
    }

    // ---- epilogue: bias (+ReLU) (+bf16 split) and store ----
    #pragma unroll
    for (int ni = 0; ni < 4; ni++) {
        int cl   = wn * 32 + ni * 8 + ((lane & 3) << 1);   // col within CTA tile
        int gcol = bn + cl;
        float2 bv = *(const float2*)(bias + gcol);
        #pragma unroll
        for (int mi = 0; mi < 4; mi++) {
            int r0 = bm + wm * 64 + mi * 16 + (lane >> 2);
            float vx0 = acc[mi][ni][0] + bv.x, vy0 = acc[mi][ni][1] + bv.y;
            float vx1 = acc[mi][ni][2] + bv.x, vy1 = acc[mi][ni][3] + bv.y;
            if (RELU) {
                vx0 = fmaxf(vx0, 0.f); vy0 = fmaxf(vy0, 0.f);
                vx1 = fmaxf(vx1, 0.f); vy1 = fmaxf(vy1, 0.f);
            }
            if (!SPLITOUT) {
                if (r0 < N)
                    *(float2*)(Cf + (size_t)r0 * ldc + ccol + gcol) = make_float2(vx0, vy0);
                if (r0 + 8 < N)
                    *(float2*)(Cf + (size_t)(r0 + 8) * ldc + ccol + gcol) = make_float2(vx1, vy1);
            } else {
                if (r0 < N) {
                    __nv_bfloat16 h0 = __float2bfloat16(vx0), h1 = __float2bfloat16(vy0);
                    __nv_bfloat16 l0 = __float2bfloat16(vx0 - __bfloat162float(h0));
                    __nv_bfloat16 l1 = __float2bfloat16(vy0 - __bfloat162float(h1));
                    __nv_bfloat162 ph(h0, h1), pl(l0, l1);
                    *(uint32_t*)(Ch + (size_t)r0 * 128 + gcol) = *(uint32_t*)&ph;
                    *(uint32_t*)(Cl + (size_t)r0 * 128 + gcol) = *(uint32_t*)&pl;
                }
                if (r0 + 8 < N) {
                    __nv_bfloat16 h0 = __float2bfloat16(vx1), h1 = __float2bfloat16(vy1);
                    __nv_bfloat16 l0 = __float2bfloat16(vx1 - __bfloat162float(h0));
                    __nv_bfloat16 l1 = __float2bfloat16(vy1 - __bfloat162float(h1));
                    __nv_bfloat162 ph(h0, h1), pl(l0, l1);
                    *(uint32_t*)(Ch + (size_t)(r0 + 8) * 128 + gcol) = *(uint32_t*)&ph;
                    *(uint32_t*)(Cl + (size_t)(r0 + 8) * 128 + gcol) = *(uint32_t*)&pl;
                }
            }
        }
    }
}

// =================== support kernels ===================
__global__ void detect_idx64(const unsigned int* __restrict__ a,
                             const unsigned int* __restrict__ b, int E)
{
    int n = E < 32 ? E : 32;
    int is64 = 1;
    for (int i = 0; i < n; i++) {
        if (a[2 * i + 1] != 0u) is64 = 0;
        if (b[2 * i + 1] != 0u) is64 = 0;
    }
    g_is64 = is64;
}

__global__ void convert_idx(const void* __restrict__ srcA, const void* __restrict__ srcB,
                            int* __restrict__ dstA, int* __restrict__ dstB, int E)
{
    int e = blockIdx.x * blockDim.x + threadIdx.x;
    if (e >= E) return;
    if (g_is64) {
        dstA[e] = (int)((const long long*)srcA)[e];
        dstB[e] = (int)((const long long*)srcB)[e];
    } else {
        dstA[e] = ((const int*)srcA)[e];
        dstB[e] = ((const int*)srcB)[e];
    }
}

__global__ void split_pair(const float* __restrict__ x,
                           __nv_bfloat16* __restrict__ xh,
                           __nv_bfloat16* __restrict__ xl, long long n4)
{
    long long i = (long long)blockIdx.x * blockDim.x + threadIdx.x;
    if (i >= n4) return;
    float4 v = *(const float4*)(x + i * 4);
    __nv_bfloat16 h0 = __float2bfloat16(v.x), h1 = __float2bfloat16(v.y);
    __nv_bfloat16 h2 = __float2bfloat16(v.z), h3 = __float2bfloat16(v.w);
    __nv_bfloat16 l0 = __float2bfloat16(v.x - __bfloat162float(h0));
    __nv_bfloat16 l1 = __float2bfloat16(v.y - __bfloat162float(h1));
    __nv_bfloat16 l2 = __float2bfloat16(v.z - __bfloat162float(h2));
    __nv_bfloat16 l3 = __float2bfloat16(v.w - __bfloat162float(h3));
    __nv_bfloat162 ph0(h0, h1), ph1(h2, h3), pl0(l0, l1), pl1(l2, l3);
    *(uint2*)(xh + i * 4) = make_uint2(*(uint32_t*)&ph0, *(uint32_t*)&ph1);
    *(uint2*)(xl + i * 4) = make_uint2(*(uint32_t*)&pl0, *(uint32_t*)&pl1);
}

__global__ void edge_aggr(const int* __restrict__ src, const int* __restrict__ dst,
                          const float* __restrict__ feat, float* __restrict__ aggr,
                          int ldc, int E, int maxS, int maxD)
{
    long long idx = (long long)blockIdx.x * blockDim.x + threadIdx.x;
    int e = (int)(idx >> 5);
    if (e >= E) return;
    int c = (int)(idx & 31) << 2;
    int s = src[e], d = dst[e];
    if ((unsigned)s >= (unsigned)maxS || (unsigned)d >= (unsigned)maxD) return;
    float4 v = *(const float4*)(feat + (size_t)s * 128 + c);
    float* p = aggr + (size_t)d * ldc + c;
    atomicAdd(p + 0, v.x);
    atomicAdd(p + 1, v.y);
    atomicAdd(p + 2, v.z);
    atomicAdd(p + 3, v.w);
}

// GRU pointwise + fused bf16 split of h'
__global__ void gru_pointwise2(const float* __restrict__ gi, const float* __restrict__ gh,
                               const float* __restrict__ h, float* __restrict__ hout,
                               __nv_bfloat16* __restrict__ hh, __nv_bfloat16* __restrict__ hl,
                               int N)
{
    long long idx = (long long)blockIdx.x * blockDim.x + threadIdx.x;
    if (idx >= (long long)N * 32) return;
    int n = (int)(idx >> 5);
    int j = (int)(idx & 31) << 2;
    const float* gip = gi + (size_t)n * 384;
    const float* ghp = gh + (size_t)n * 384;
    float4 giR = *(const float4*)(gip + j);
    float4 giZ = *(const float4*)(gip + 128 + j);
    float4 giN = *(const float4*)(gip + 256 + j);
    float4 ghR = *(const float4*)(ghp + j);
    float4 ghZ = *(const float4*)(ghp + 128 + j);
    float4 ghN = *(const float4*)(ghp + 256 + j);
    float4 hv = *(const float4*)(h + (size_t)n * 128 + j);

    float4 o;
    {
        float r = 1.f / (1.f + expf(-(giR.x + ghR.x)));
        float z = 1.f / (1.f + expf(-(giZ.x + ghZ.x)));
        float nn = tanhf(giN.x + r * ghN.x);
        o.x = (1.f - z) * nn + z * hv.x;
    }
    {
        float r = 1.f / (1.f + expf(-(giR.y + ghR.y)));
        float z = 1.f / (1.f + expf(-(giZ.y + ghZ.y)));
        float nn = tanhf(giN.y + r * ghN.y);
        o.y = (1.f - z) * nn + z * hv.y;
    }
    {
        float r = 1.f / (1.f + expf(-(giR.z + ghR.z)));
        float z = 1.f / (1.f + expf(-(giZ.z + ghZ.z)));
        float nn = tanhf(giN.z + r * ghN.z);
        o.z = (1.f - z) * nn + z * hv.z;
    }
    {
        float r = 1.f / (1.f + expf(-(giR.w + ghR.w)));
        float z = 1.f / (1.f + expf(-(giZ.w + ghZ.w)));
        float nn = tanhf(giN.w + r * ghN.w);
        o.w = (1.f - z) * nn + z * hv.w;
    }
    *(float4*)(hout + (size_t)n * 128 + j) = o;

    __nv_bfloat16 h0 = __float2bfloat16(o.x), h1 = __float2bfloat16(o.y);
    __nv_bfloat16 h2 = __float2bfloat16(o.z), h3 = __float2bfloat16(o.w);
    __nv_bfloat16 l0 = __float2bfloat16(o.x - __bfloat162float(h0));
    __nv_bfloat16 l1 = __float2bfloat16(o.y - __bfloat162float(h1));
    __nv_bfloat16 l2 = __float2bfloat16(o.z - __bfloat162float(h2));
    __nv_bfloat16 l3 = __float2bfloat16(o.w - __bfloat162float(h3));
    __nv_bfloat162 ph0(h0, h1), ph1(h2, h3), pl0(l0, l1), pl1(l2, l3);
    *(uint2*)(hh + (size_t)n * 128 + j) = make_uint2(*(uint32_t*)&ph0, *(uint32_t*)&ph1);
    *(uint2*)(hl + (size_t)n * 128 + j) = make_uint2(*(uint32_t*)&pl0, *(uint32_t*)&pl1);
}

// =================== host side ===================
static void tgemm(int xorr, int splitout,
                  const __nv_bfloat16* Ah, const __nv_bfloat16* Al,
                  const __nv_bfloat16* Wh, const __nv_bfloat16* Wl,
                  const float* bias, float* Cf,
                  __nv_bfloat16* Ch, __nv_bfloat16* Cl,
                  int ldc, int ccol, int N, int M, int K)
{
    dim3 grid((N + 127) / 128, M / 128);
    if (splitout) {
        if (xorr)
            mma_gemm<1, 1, 1><<<grid, 256, SMEM_BYTES>>>(Ah, Al, Wh, Wl, bias, Cf, Ch, Cl, ldc, ccol, N, M, K);
        else
            mma_gemm<1, 0, 1><<<grid, 256, SMEM_BYTES>>>(Ah, Al, Wh, Wl, bias, Cf, Ch, Cl, ldc, ccol, N, M, K);
    } else {
        mma_gemm<0, 0, 0><<<grid, 256, SMEM_BYTES>>>(Ah, Al, Wh, Wl, bias, Cf, Ch, Cl, ldc, ccol, N, M, K);
    }
}

static void splitN(const float* x, __nv_bfloat16* xh, __nv_bfloat16* xl, long long n)
{
    long long n4 = n / 4;
    split_pair<<<(int)((n4 + 255) / 256), 256>>>(x, xh, xl, n4);
}

extern "C" void kernel_launch(void* const* d_in, const int* in_sizes, int n_in,
                              void* d_out, int out_size)
{
    int base = (n_in >= 26) ? 2 : 0;

    const void*  l_ei_raw = d_in[base + 0];
    const void*  c_ei_raw = d_in[base + 1];
    const float* l_emb0   = (const float*)d_in[base + 2];
    const float* c_emb0   = (const float*)d_in[base + 3];

    const float* Wsrc[10] = {
        (const float*)d_in[base + 4],  (const float*)d_in[base + 6],
        (const float*)d_in[base + 8],  (const float*)d_in[base + 10],
        (const float*)d_in[base + 12], (const float*)d_in[base + 14],
        (const float*)d_in[base + 16], (const float*)d_in[base + 17],
        (const float*)d_in[base + 20], (const float*)d_in[base + 21],
    };
    const int Wcnt[10] = {16384, 16384, 16384, 16384, 16384, 16384,
                          49152, 49152, 98304, 49152};
    const float* l2c_b1 = (const float*)d_in[base + 5];
    const float* l2c_b2 = (const float*)d_in[base + 7];
    const float* c2l_b1 = (const float*)d_in[base + 9];
    const float* c2l_b2 = (const float*)d_in[base + 11];
    const float* l2l_b1 = (const float*)d_in[base + 13];
    const float* l2l_b2 = (const float*)d_in[base + 15];
    const float* cgru_bih = (const float*)d_in[base + 18];
    const float* cgru_bhh = (const float*)d_in[base + 19];
    const float* lgru_bih = (const float*)d_in[base + 22];
    const float* lgru_bhh = (const float*)d_in[base + 23];

    const int E = in_sizes[base + 0];
    const int L = in_sizes[base + 2] / DIM;
    const int C = in_sizes[base + 3] / DIM;

    float* out   = (float*)d_out;
    float* l_out = out;
    float* c_out = out + (size_t)(NITER + 1) * L * DIM;

    float *lfeat, *cfeat, *caggr, *lx, *gi, *gh;
    int *lei, *cei;
    __nv_bfloat16 *lch, *lcl, *cch, *ccl, *hidh, *hidl, *cagh, *cagl, *lxh, *lxl, *wh, *wl;
    cudaGetSymbolAddress((void**)&lfeat, g_lfeat);
    cudaGetSymbolAddress((void**)&cfeat, g_cfeat);
    cudaGetSymbolAddress((void**)&caggr, g_caggr);
    cudaGetSymbolAddress((void**)&lx,    g_lx);
    cudaGetSymbolAddress((void**)&gi,    g_gi);
    cudaGetSymbolAddress((void**)&gh,    g_gh);
    cudaGetSymbolAddress((void**)&lei,   g_lei32);
    cudaGetSymbolAddress((void**)&cei,   g_cei32);
    cudaGetSymbolAddress((void**)&lch,   g_lcur_h);
    cudaGetSymbolAddress((void**)&lcl,   g_lcur_l);
    cudaGetSymbolAddress((void**)&cch,   g_ccur_h);
    cudaGetSymbolAddress((void**)&ccl,   g_ccur_l);
    cudaGetSymbolAddress((void**)&hidh,  g_hid_h);
    cudaGetSymbolAddress((void**)&hidl,  g_hid_l);
    cudaGetSymbolAddress((void**)&cagh,  g_cag_h);
    cudaGetSymbolAddress((void**)&cagl,  g_cag_l);
    cudaGetSymbolAddress((void**)&lxh,   g_lxs_h);
    cudaGetSymbolAddress((void**)&lxl,   g_lxs_l);
    cudaGetSymbolAddress((void**)&wh,    g_w_h);
    cudaGetSymbolAddress((void**)&wl,    g_w_l);

    cudaFuncSetAttribute((const void*)mma_gemm<1, 0, 1>, cudaFuncAttributeMaxDynamicSharedMemorySize, SMEM_BYTES);
    cudaFuncSetAttribute((const void*)mma_gemm<1, 1, 1>, cudaFuncAttributeMaxDynamicSharedMemorySize, SMEM_BYTES);
    cudaFuncSetAttribute((const void*)mma_gemm<0, 0, 0>, cudaFuncAttributeMaxDynamicSharedMemorySize, SMEM_BYTES);

    detect_idx64<<<1, 1>>>((const unsigned int*)l_ei_raw, (const unsigned int*)c_ei_raw, E);
    convert_idx<<<(E + 255) / 256, 256>>>(l_ei_raw, c_ei_raw, lei, cei, E);

    long long woff = 0;
    __nv_bfloat16 *Wh_[10], *Wl_[10];
    for (int i = 0; i < 10; i++) {
        Wh_[i] = wh + woff;
        Wl_[i] = wl + woff;
        splitN(Wsrc[i], Wh_[i], Wl_[i], Wcnt[i]);
        woff += Wcnt[i];
    }

    cudaMemcpyAsync(l_out, l_emb0, (size_t)L * DIM * sizeof(float), cudaMemcpyDeviceToDevice, 0);
    cudaMemcpyAsync(c_out, c_emb0, (size_t)C * DIM * sizeof(float), cudaMemcpyDeviceToDevice, 0);
    splitN(l_emb0, lch, lcl, (long long)L * DIM);
    splitN(c_emb0, cch, ccl, (long long)C * DIM);

    const int edge_blocks = (int)(((long long)E * 32 + 255) / 256);

    for (int it = 0; it < NITER; it++) {
        const float* lcur = l_out + (size_t)it * L * DIM;
        const float* ccur = c_out + (size_t)it * C * DIM;
        float* lnext = l_out + (size_t)(it + 1) * L * DIM;
        float* cnext = c_out + (size_t)(it + 1) * C * DIM;

        // --- l2c MLP ---
        tgemm(0, 1, lch, lcl, Wh_[0], Wl_[0], l2c_b1, nullptr, hidh, hidl, 128, 0, L, 128, 128);
        tgemm(0, 0, hidh, hidl, Wh_[1], Wl_[1], l2c_b2, lfeat, nullptr, nullptr, 128, 0, L, 128, 128);

        // --- c2l MLP ---
        tgemm(0, 1, cch, ccl, Wh_[2], Wl_[2], c2l_b1, nullptr, hidh, hidl, 128, 0, C, 128, 128);
        tgemm(0, 0, hidh, hidl, Wh_[3], Wl_[3], c2l_b2, cfeat, nullptr, nullptr, 128, 0, C, 128, 128);

        // --- l2l MLP (polarity flip at A load) -> lx cols [128..255] ---
        cudaMemsetAsync(lx, 0, (size_t)L * 256 * sizeof(float), 0);
        tgemm(1, 1, lch, lcl, Wh_[4], Wl_[4], l2l_b1, nullptr, hidh, hidl, 128, 0, L, 128, 128);
        tgemm(0, 0, hidh, hidl, Wh_[5], Wl_[5], l2l_b2, lx, nullptr, nullptr, 256, 128, L, 128, 128);

        // --- fused gather + segment sums ---
        cudaMemsetAsync(caggr, 0, (size_t)C * DIM * sizeof(float), 0);
        edge_aggr<<<edge_blocks, 256>>>(lei, cei, lfeat, caggr, 128, E, L, C);
        edge_aggr<<<edge_blocks, 256>>>(cei, lei, cfeat, lx, 256, E, C, L);

        // --- clause GRU ---
        splitN(caggr, cagh, cagl, (long long)C * 128);
        tgemm(0, 0, cagh, cagl, Wh_[6], Wl_[6], cgru_bih, gi, nullptr, nullptr, 384, 0, C, 384, 128);
        tgemm(0, 0, cch, ccl, Wh_[7], Wl_[7], cgru_bhh, gh, nullptr, nullptr, 384, 0, C, 384, 128);
        {
            long long tot = (long long)C * 32;
            gru_pointwise2<<<(int)((tot + 255) / 256), 256>>>(gi, gh, ccur, cnext, cch, ccl, C);
        }

        // --- literal GRU (K=256 for gi) ---
        splitN(lx, lxh, lxl, (long long)L * 256);
        tgemm(0, 0, lxh, lxl, Wh_[8], Wl_[8], lgru_bih, gi, nullptr, nullptr, 384, 0, L, 384, 256);
        tgemm(0, 0, lch, lcl, Wh_[9], Wl_[9], lgru_bhh, gh, nullptr, nullptr, 384, 0, L, 384, 128);
        {
            long long tot = (long long)L * 32;
            gru_pointwise2<<<(int)((tot + 255) / 256), 256>>>(gi, gh, lcur, lnext, lch, lcl, L);
        }
    }
}

// round 6
// speedup vs baseline: 2.5644x; 1.1069x over previous
#include <cuda_runtime.h>
#include <cuda_bf16.h>
#include <math.h>
#include <stdint.h>

#define DIM 128
#define NITER 8

#define MAXL 100096ull
#define MAXC 150016ull
#define MAXN 150016ull
#define MAXE 450048

// ---------------- fp32 scratch ----------------
__device__ float g_lfeat[MAXL * 128];
__device__ float g_cfeat[MAXC * 128];
__device__ float g_caggr[MAXC * 128];
__device__ float g_lx0  [MAXL * 128];   // c2l segment sum
__device__ float g_l2lm [MAXL * 128];   // l2l message (MLP out)
__device__ float g_gi   [MAXN * 384];
__device__ float g_gh   [MAXN * 384];
__device__ int   g_lei32[MAXE];
__device__ int   g_cei32[MAXE];
__device__ int   g_is64;

// ---------------- bf16 split scratch (hi/lo) ----------------
__device__ __nv_bfloat16 g_lcur_h[MAXL * 128], g_lcur_l[MAXL * 128];
__device__ __nv_bfloat16 g_ccur_h[MAXC * 128], g_ccur_l[MAXC * 128];
__device__ __nv_bfloat16 g_hid_h [MAXN * 128], g_hid_l [MAXN * 128];
#define WPOOL 344064
__device__ __nv_bfloat16 g_w_h[WPOOL], g_w_l[WPOOL];

// =================== helpers ===================
__device__ __forceinline__ uint32_t smem_to_u32(const void* p) {
    uint32_t a;
    asm("{ .reg .u64 t; cvta.to.shared.u64 t, %1; cvt.u32.u64 %0, t; }"
        : "=r"(a) : "l"(p));
    return a;
}
__device__ __forceinline__ void ldx4(uint32_t* r, uint32_t addr) {
    asm volatile("ldmatrix.sync.aligned.m8n8.x4.shared.b16 {%0,%1,%2,%3}, [%4];"
                 : "=r"(r[0]), "=r"(r[1]), "=r"(r[2]), "=r"(r[3]) : "r"(addr));
}
__device__ __forceinline__ void ldx2(uint32_t* r, uint32_t addr) {
    asm volatile("ldmatrix.sync.aligned.m8n8.x2.shared.b16 {%0,%1}, [%2];"
                 : "=r"(r[0]), "=r"(r[1]) : "r"(addr));
}
__device__ __forceinline__ void mma_bf16(float* d, const uint32_t* a, const uint32_t* b) {
    asm volatile("mma.sync.aligned.m16n8k16.row.col.f32.bf16.bf16.f32 "
                 "{%0,%1,%2,%3}, {%4,%5,%6,%7}, {%8,%9}, {%0,%1,%2,%3};"
                 : "+f"(d[0]), "+f"(d[1]), "+f"(d[2]), "+f"(d[3])
                 : "r"(a[0]), "r"(a[1]), "r"(a[2]), "r"(a[3]), "r"(b[0]), "r"(b[1]));
}
__device__ __forceinline__ uint32_t pack_h(float x, float y) {
    __nv_bfloat162 p(__float2bfloat16(x), __float2bfloat16(y));
    return *(uint32_t*)&p;
}
__device__ __forceinline__ uint32_t pack_l(float x, float y) {
    __nv_bfloat16 hx = __float2bfloat16(x), hy = __float2bfloat16(y);
    __nv_bfloat162 p(__float2bfloat16(x - __bfloat162float(hx)),
                     __float2bfloat16(y - __bfloat162float(hy)));
    return *(uint32_t*)&p;
}

// smem geometry: 4 matrices (ah, al, wh, wl) of 128 rows x 144B
#define MAT_BYTES 18432
#define SMEM_BYTES 73728

// =================== split-bf16 GEMM via mma.sync ===================
// Y[N, M] = act( A[N,K] @ W[M,K]^T + bias ),  A = Ah+Al (A16) or fp32 (A32)
// grid = (ceil(N/128), M/128), 256 threads (8 warps, 2x4 of 64x32 tiles)
template<int RELU, int XORROW, int SPLITOUT, int A32, int DUAL>
__global__ __launch_bounds__(256, 2)
void mma_gemm(const __nv_bfloat16* __restrict__ Ah, const __nv_bfloat16* __restrict__ Al,
              const float* __restrict__ Af0, const float* __restrict__ Af1,
              const __nv_bfloat16* __restrict__ Wh, const __nv_bfloat16* __restrict__ Wl,
              const float* __restrict__ bias,
              float* __restrict__ Cf,
              __nv_bfloat16* __restrict__ Ch, __nv_bfloat16* __restrict__ Cl,
              int ldc, int ccol, int N, int M, int K)
{
    extern __shared__ char smem[];
    const uint32_t sb = smem_to_u32(smem);
    const int tid  = threadIdx.x;
    const int lane = tid & 31;
    const int wid  = tid >> 5;
    const int wm   = wid >> 2;
    const int wn   = wid & 3;
    const int bm   = blockIdx.x * 128;
    const int bn   = blockIdx.y * 128;
    const int nchunk = K >> 6;

    float acc[4][4][4] = {};

    const uint32_t aBase = sb + (uint32_t)(wm * 64 + (lane & 15)) * 144 + ((lane >> 4) << 4);
    const uint32_t bBase = sb + 2 * MAT_BYTES
                         + (uint32_t)(wn * 32 + (lane & 7)) * 144 + (((lane >> 3) & 1) << 4);

    for (int kc = 0; kc < nchunk; kc++) {
        if (kc) __syncthreads();                 // WAR: previous mma done
        const int k0 = kc << 6;
        #pragma unroll
        for (int t = 0; t < 4; t++) {
            int i    = tid + (t << 8);           // 0..1023
            int row  = i >> 3;                   // 0..127
            int unit = i & 7;                    // 16B unit within 128B bf16 row
            char* dst = smem + (size_t)row * 144 + (unit << 4);

            int grow = bm + row;
            if (A32) {
                float4 f0 = make_float4(0.f, 0.f, 0.f, 0.f);
                float4 f1 = f0;
                if (grow < N) {
                    int sr = XORROW ? (grow ^ 1) : grow;
                    const float* src;
                    if (DUAL)
                        src = (k0 < 128) ? (Af0 + (size_t)sr * 128 + k0)
                                         : (Af1 + (size_t)sr * 128 + (k0 - 128));
                    else
                        src = Af0 + (size_t)sr * K + k0;
                    f0 = *((const float4*)src + unit * 2);
                    f1 = *((const float4*)src + unit * 2 + 1);
                }
                uint4 vh, vl;
                vh.x = pack_h(f0.x, f0.y); vl.x = pack_l(f0.x, f0.y);
                vh.y = pack_h(f0.z, f0.w); vl.y = pack_l(f0.z, f0.w);
                vh.z = pack_h(f1.x, f1.y); vl.z = pack_l(f1.x, f1.y);
                vh.w = pack_h(f1.z, f1.w); vl.w = pack_l(f1.z, f1.w);
                *(uint4*)dst               = vh;
                *(uint4*)(dst + MAT_BYTES) = vl;
            } else {
                uint4 vh = make_uint4(0, 0, 0, 0), vl = vh;
                if (grow < N) {
                    int sr = XORROW ? (grow ^ 1) : grow;
                    vh = *((const uint4*)(Ah + (size_t)sr * K + k0) + unit);
                    vl = *((const uint4*)(Al + (size_t)sr * K + k0) + unit);
                }
                *(uint4*)dst               = vh;
                *(uint4*)(dst + MAT_BYTES) = vl;
            }
            int brow = bn + row;
            *(uint4*)(dst + 2 * MAT_BYTES) = *((const uint4*)(Wh + (size_t)brow * K + k0) + unit);
            *(uint4*)(dst + 3 * MAT_BYTES) = *((const uint4*)(Wl + (size_t)brow * K + k0) + unit);
        }
        __syncthreads();

        #pragma unroll
        for (int k16 = 0; k16 < 4; k16++) {
            const uint32_t kb = k16 << 5;
            uint32_t ah[4][4], al[4][4];
            #pragma unroll
            for (int mi = 0; mi < 4; mi++) {
                ldx4(ah[mi], aBase + mi * (16 * 144) + kb);
                ldx4(al[mi], aBase + MAT_BYTES + mi * (16 * 144) + kb);
            }
            #pragma unroll
            for (int ni = 0; ni < 4; ni++) {
                uint32_t bh[2], bl[2];
                ldx2(bh, bBase + ni * (8 * 144) + kb);
                ldx2(bl, bBase + MAT_BYTES + ni * (8 * 144) + kb);
                #pragma unroll
                for (int mi = 0; mi < 4; mi++) {
                    mma_bf16(acc[mi][ni], ah[mi], bh);
                    mma_bf16(acc[mi][ni], al[mi], bh);
                    mma_bf16(acc[mi][ni], ah[mi], bl);
                }
            }
        }
    }

    // ---- epilogue ----
    #pragma unroll
    for (int ni = 0; ni < 4; ni++) {
        int cl   = wn * 32 + ni * 8 + ((lane & 3) << 1);
        int gcol = bn + cl;
        float2 bv = *(const float2*)(bias + gcol);
        #pragma unroll
        for (int mi = 0; mi < 4; mi++) {
            int r0 = bm + wm * 64 + mi * 16 + (lane >> 2);
            float vx0 = acc[mi][ni][0] + bv.x, vy0 = acc[mi][ni][1] + bv.y;
            float vx1 = acc[mi][ni][2] + bv.x, vy1 = acc[mi][ni][3] + bv.y;
            if (RELU) {
                vx0 = fmaxf(vx0, 0.f); vy0 = fmaxf(vy0, 0.f);
                vx1 = fmaxf(vx1, 0.f); vy1 = fmaxf(vy1, 0.f);
            }
            if (!SPLITOUT) {
                if (r0 < N)
                    *(float2*)(Cf + (size_t)r0 * ldc + ccol + gcol) = make_float2(vx0, vy0);
                if (r0 + 8 < N)
                    *(float2*)(Cf + (size_t)(r0 + 8) * ldc + ccol + gcol) = make_float2(vx1, vy1);
            } else {
                if (r0 < N) {
                    uint32_t uh = pack_h(vx0, vy0), ul = pack_l(vx0, vy0);
                    *(uint32_t*)(Ch + (size_t)r0 * 128 + gcol) = uh;
                    *(uint32_t*)(Cl + (size_t)r0 * 128 + gcol) = ul;
                }
                if (r0 + 8 < N) {
                    uint32_t uh = pack_h(vx1, vy1), ul = pack_l(vx1, vy1);
                    *(uint32_t*)(Ch + (size_t)(r0 + 8) * 128 + gcol) = uh;
                    *(uint32_t*)(Cl + (size_t)(r0 + 8) * 128 + gcol) = ul;
                }
            }
        }
    }
}

// =================== support kernels ===================
__global__ void detect_idx64(const unsigned int* __restrict__ a,
                             const unsigned int* __restrict__ b, int E)
{
    int n = E < 32 ? E : 32;
    int is64 = 1;
    for (int i = 0; i < n; i++) {
        if (a[2 * i + 1] != 0u) is64 = 0;
        if (b[2 * i + 1] != 0u) is64 = 0;
    }
    g_is64 = is64;
}

__global__ void convert_idx(const void* __restrict__ srcA, const void* __restrict__ srcB,
                            int* __restrict__ dstA, int* __restrict__ dstB, int E)
{
    int e = blockIdx.x * blockDim.x + threadIdx.x;
    if (e >= E) return;
    if (g_is64) {
        dstA[e] = (int)((const long long*)srcA)[e];
        dstB[e] = (int)((const long long*)srcB)[e];
    } else {
        dstA[e] = ((const int*)srcA)[e];
        dstB[e] = ((const int*)srcB)[e];
    }
}

struct WSplitArgs {
    const float4* src[10];
    int start4[11];     // cumulative float4 offsets
};

__global__ void wsplit_all(WSplitArgs a, __nv_bfloat16* __restrict__ wh,
                           __nv_bfloat16* __restrict__ wl)
{
    int i = blockIdx.x * blockDim.x + threadIdx.x;
    if (i >= a.start4[10]) return;
    int m = 0;
    while (i >= a.start4[m + 1]) m++;
    float4 v = a.src[m][i - a.start4[m]];
    uint2 uh = make_uint2(pack_h(v.x, v.y), pack_h(v.z, v.w));
    uint2 ul = make_uint2(pack_l(v.x, v.y), pack_l(v.z, v.w));
    *(uint2*)(wh + (size_t)i * 4) = uh;
    *(uint2*)(wl + (size_t)i * 4) = ul;
}

__global__ void split_pair(const float* __restrict__ x,
                           __nv_bfloat16* __restrict__ xh,
                           __nv_bfloat16* __restrict__ xl, long long n4)
{
    long long i = (long long)blockIdx.x * blockDim.x + threadIdx.x;
    if (i >= n4) return;
    float4 v = *(const float4*)(x + i * 4);
    *(uint2*)(xh + i * 4) = make_uint2(pack_h(v.x, v.y), pack_h(v.z, v.w));
    *(uint2*)(xl + i * 4) = make_uint2(pack_l(v.x, v.y), pack_l(v.z, v.w));
}

__global__ void edge_aggr(const int* __restrict__ src, const int* __restrict__ dst,
                          const float* __restrict__ feat, float* __restrict__ aggr,
                          int E, int maxS, int maxD)
{
    long long idx = (long long)blockIdx.x * blockDim.x + threadIdx.x;
    int e = (int)(idx >> 5);
    if (e >= E) return;
    int c = (int)(idx & 31) << 2;
    int s = src[e], d = dst[e];
    if ((unsigned)s >= (unsigned)maxS || (unsigned)d >= (unsigned)maxD) return;
    float4 v = *(const float4*)(feat + (size_t)s * 128 + c);
    float* p = aggr + (size_t)d * 128 + c;
    atomicAdd(p + 0, v.x);
    atomicAdd(p + 1, v.y);
    atomicAdd(p + 2, v.z);
    atomicAdd(p + 3, v.w);
}

__global__ void gru_pointwise2(const float* __restrict__ gi, const float* __restrict__ gh,
                               const float* __restrict__ h, float* __restrict__ hout,
                               __nv_bfloat16* __restrict__ hh, __nv_bfloat16* __restrict__ hl,
                               int N)
{
    long long idx = (long long)blockIdx.x * blockDim.x + threadIdx.x;
    if (idx >= (long long)N * 32) return;
    int n = (int)(idx >> 5);
    int j = (int)(idx & 31) << 2;
    const float* gip = gi + (size_t)n * 384;
    const float* ghp = gh + (size_t)n * 384;
    float4 giR = *(const float4*)(gip + j);
    float4 giZ = *(const float4*)(gip + 128 + j);
    float4 giN = *(const float4*)(gip + 256 + j);
    float4 ghR = *(const float4*)(ghp + j);
    float4 ghZ = *(const float4*)(ghp + 128 + j);
    float4 ghN = *(const float4*)(ghp + 256 + j);
    float4 hv = *(const float4*)(h + (size_t)n * 128 + j);

    float4 o;
    {
        float r = 1.f / (1.f + expf(-(giR.x + ghR.x)));
        float z = 1.f / (1.f + expf(-(giZ.x + ghZ.x)));
        float nn = tanhf(giN.x + r * ghN.x);
        o.x = (1.f - z) * nn + z * hv.x;
    }
    {
        float r = 1.f / (1.f + expf(-(giR.y + ghR.y)));
        float z = 1.f / (1.f + expf(-(giZ.y + ghZ.y)));
        float nn = tanhf(giN.y + r * ghN.y);
        o.y = (1.f - z) * nn + z * hv.y;
    }
    {
        float r = 1.f / (1.f + expf(-(giR.z + ghR.z)));
        float z = 1.f / (1.f + expf(-(giZ.z + ghZ.z)));
        float nn = tanhf(giN.z + r * ghN.z);
        o.z = (1.f - z) * nn + z * hv.z;
    }
    {
        float r = 1.f / (1.f + expf(-(giR.w + ghR.w)));
        float z = 1.f / (1.f + expf(-(giZ.w + ghZ.w)));
        float nn = tanhf(giN.w + r * ghN.w);
        o.w = (1.f - z) * nn + z * hv.w;
    }
    *(float4*)(hout + (size_t)n * 128 + j) = o;
    *(uint2*)(hh + (size_t)n * 128 + j) = make_uint2(pack_h(o.x, o.y), pack_h(o.z, o.w));
    *(uint2*)(hl + (size_t)n * 128 + j) = make_uint2(pack_l(o.x, o.y), pack_l(o.z, o.w));
}

// =================== host side ===================
extern "C" void kernel_launch(void* const* d_in, const int* in_sizes, int n_in,
                              void* d_out, int out_size)
{
    int base = (n_in >= 26) ? 2 : 0;

    const void*  l_ei_raw = d_in[base + 0];
    const void*  c_ei_raw = d_in[base + 1];
    const float* l_emb0   = (const float*)d_in[base + 2];
    const float* c_emb0   = (const float*)d_in[base + 3];

    const float* Wsrc[10] = {
        (const float*)d_in[base + 4],  (const float*)d_in[base + 6],
        (const float*)d_in[base + 8],  (const float*)d_in[base + 10],
        (const float*)d_in[base + 12], (const float*)d_in[base + 14],
        (const float*)d_in[base + 16], (const float*)d_in[base + 17],
        (const float*)d_in[base + 20], (const float*)d_in[base + 21],
    };
    const int Wcnt[10] = {16384, 16384, 16384, 16384, 16384, 16384,
                          49152, 49152, 98304, 49152};
    const float* l2c_b1 = (const float*)d_in[base + 5];
    const float* l2c_b2 = (const float*)d_in[base + 7];
    const float* c2l_b1 = (const float*)d_in[base + 9];
    const float* c2l_b2 = (const float*)d_in[base + 11];
    const float* l2l_b1 = (const float*)d_in[base + 13];
    const float* l2l_b2 = (const float*)d_in[base + 15];
    const float* cgru_bih = (const float*)d_in[base + 18];
    const float* cgru_bhh = (const float*)d_in[base + 19];
    const float* lgru_bih = (const float*)d_in[base + 22];
    const float* lgru_bhh = (const float*)d_in[base + 23];

    const int E = in_sizes[base + 0];
    const int L = in_sizes[base + 2] / DIM;
    const int C = in_sizes[base + 3] / DIM;

    float* out   = (float*)d_out;
    float* l_out = out;
    float* c_out = out + (size_t)(NITER + 1) * L * DIM;

    float *lfeat, *cfeat, *caggr, *lx0, *l2lm, *gi, *gh;
    int *lei, *cei;
    __nv_bfloat16 *lch, *lcl, *cch, *ccl, *hidh, *hidl, *wh, *wl;
    cudaGetSymbolAddress((void**)&lfeat, g_lfeat);
    cudaGetSymbolAddress((void**)&cfeat, g_cfeat);
    cudaGetSymbolAddress((void**)&caggr, g_caggr);
    cudaGetSymbolAddress((void**)&lx0,   g_lx0);
    cudaGetSymbolAddress((void**)&l2lm,  g_l2lm);
    cudaGetSymbolAddress((void**)&gi,    g_gi);
    cudaGetSymbolAddress((void**)&gh,    g_gh);
    cudaGetSymbolAddress((void**)&lei,   g_lei32);
    cudaGetSymbolAddress((void**)&cei,   g_cei32);
    cudaGetSymbolAddress((void**)&lch,   g_lcur_h);
    cudaGetSymbolAddress((void**)&lcl,   g_lcur_l);
    cudaGetSymbolAddress((void**)&cch,   g_ccur_h);
    cudaGetSymbolAddress((void**)&ccl,   g_ccur_l);
    cudaGetSymbolAddress((void**)&hidh,  g_hid_h);
    cudaGetSymbolAddress((void**)&hidl,  g_hid_l);
    cudaGetSymbolAddress((void**)&wh,    g_w_h);
    cudaGetSymbolAddress((void**)&wl,    g_w_l);

    cudaFuncSetAttribute((const void*)mma_gemm<1, 0, 1, 0, 0>, cudaFuncAttributeMaxDynamicSharedMemorySize, SMEM_BYTES);
    cudaFuncSetAttribute((const void*)mma_gemm<1, 1, 1, 0, 0>, cudaFuncAttributeMaxDynamicSharedMemorySize, SMEM_BYTES);
    cudaFuncSetAttribute((const void*)mma_gemm<0, 0, 0, 0, 0>, cudaFuncAttributeMaxDynamicSharedMemorySize, SMEM_BYTES);
    cudaFuncSetAttribute((const void*)mma_gemm<0, 0, 0, 1, 0>, cudaFuncAttributeMaxDynamicSharedMemorySize, SMEM_BYTES);
    cudaFuncSetAttribute((const void*)mma_gemm<0, 0, 0, 1, 1>, cudaFuncAttributeMaxDynamicSharedMemorySize, SMEM_BYTES);

    // prelude kernels: exactly 5 before first GEMM (ncu -s 5 lands on GEMM)
    detect_idx64<<<1, 1>>>((const unsigned int*)l_ei_raw, (const unsigned int*)c_ei_raw, E);
    convert_idx<<<(E + 255) / 256, 256>>>(l_ei_raw, c_ei_raw, lei, cei, E);

    WSplitArgs wa;
    {
        int cum = 0;
        for (int i = 0; i < 10; i++) {
            wa.src[i] = (const float4*)Wsrc[i];
            wa.start4[i] = cum;
            cum += Wcnt[i] / 4;
        }
        wa.start4[10] = cum;    // 86016
    }
    wsplit_all<<<(86016 + 255) / 256, 256>>>(wa, wh, wl);

    split_pair<<<(int)(((long long)L * 32 + 255) / 256), 256>>>(l_emb0, lch, lcl, (long long)L * 32);
    split_pair<<<(int)(((long long)C * 32 + 255) / 256), 256>>>(c_emb0, cch, ccl, (long long)C * 32);

    cudaMemcpyAsync(l_out, l_emb0, (size_t)L * DIM * sizeof(float), cudaMemcpyDeviceToDevice, 0);
    cudaMemcpyAsync(c_out, c_emb0, (size_t)C * DIM * sizeof(float), cudaMemcpyDeviceToDevice, 0);

    __nv_bfloat16 *Wh_[10], *Wl_[10];
    {
        long long woff = 0;
        for (int i = 0; i < 10; i++) {
            Wh_[i] = wh + woff;
            Wl_[i] = wl + woff;
            woff += Wcnt[i];
        }
    }

    const int edge_blocks = (int)(((long long)E * 32 + 255) / 256);
    const __nv_bfloat16* nbp = nullptr;   // null const bf16 (unused A inputs)
    const float* nfp = nullptr;           // null const float (unused A inputs)
    __nv_bfloat16* nbw = nullptr;         // null non-const bf16 (unused Ch/Cl outputs)
    float* nfw = nullptr;                 // null non-const float (unused Cf output)

    for (int it = 0; it < NITER; it++) {
        const float* lcur = l_out + (size_t)it * L * DIM;
        const float* ccur = c_out + (size_t)it * C * DIM;
        float* lnext = l_out + (size_t)(it + 1) * L * DIM;
        float* cnext = c_out + (size_t)(it + 1) * C * DIM;

        dim3 gl((L + 127) / 128, 1), gc((C + 127) / 128, 1);
        dim3 gl3((L + 127) / 128, 3), gc3((C + 127) / 128, 3);

        // --- l2c MLP ---
        mma_gemm<1, 0, 1, 0, 0><<<gl, 256, SMEM_BYTES>>>(lch, lcl, nfp, nfp, Wh_[0], Wl_[0], l2c_b1,
                                                         nfw, hidh, hidl, 128, 0, L, 128, 128);
        mma_gemm<0, 0, 0, 0, 0><<<gl, 256, SMEM_BYTES>>>(hidh, hidl, nfp, nfp, Wh_[1], Wl_[1], l2c_b2,
                                                         lfeat, nbw, nbw, 128, 0, L, 128, 128);
        // --- c2l MLP ---
        mma_gemm<1, 0, 1, 0, 0><<<gc, 256, SMEM_BYTES>>>(cch, ccl, nfp, nfp, Wh_[2], Wl_[2], c2l_b1,
                                                         nfw, hidh, hidl, 128, 0, C, 128, 128);
        mma_gemm<0, 0, 0, 0, 0><<<gc, 256, SMEM_BYTES>>>(hidh, hidl, nfp, nfp, Wh_[3], Wl_[3], c2l_b2,
                                                         cfeat, nbw, nbw, 128, 0, C, 128, 128);
        // --- l2l MLP (polarity flip at A load) ---
        mma_gemm<1, 1, 1, 0, 0><<<gl, 256, SMEM_BYTES>>>(lch, lcl, nfp, nfp, Wh_[4], Wl_[4], l2l_b1,
                                                         nfw, hidh, hidl, 128, 0, L, 128, 128);
        mma_gemm<0, 0, 0, 0, 0><<<gl, 256, SMEM_BYTES>>>(hidh, hidl, nfp, nfp, Wh_[5], Wl_[5], l2l_b2,
                                                         l2lm, nbw, nbw, 128, 0, L, 128, 128);

        // --- fused gather + segment sums ---
        cudaMemsetAsync(caggr, 0, (size_t)C * 128 * sizeof(float), 0);
        cudaMemsetAsync(lx0,   0, (size_t)L * 128 * sizeof(float), 0);
        edge_aggr<<<edge_blocks, 256>>>(lei, cei, lfeat, caggr, E, L, C);
        edge_aggr<<<edge_blocks, 256>>>(cei, lei, cfeat, lx0,   E, C, L);

        // --- clause GRU (gi from fp32 caggr via fused split) ---
        mma_gemm<0, 0, 0, 1, 0><<<gc3, 256, SMEM_BYTES>>>(nbp, nbp, caggr, nfp, Wh_[6], Wl_[6], cgru_bih,
                                                          gi, nbw, nbw, 384, 0, C, 384, 128);
        mma_gemm<0, 0, 0, 0, 0><<<gc3, 256, SMEM_BYTES>>>(cch, ccl, nfp, nfp, Wh_[7], Wl_[7], cgru_bhh,
                                                          gh, nbw, nbw, 384, 0, C, 384, 128);
        {
            long long tot = (long long)C * 32;
            gru_pointwise2<<<(int)((tot + 255) / 256), 256>>>(gi, gh, ccur, cnext, cch, ccl, C);
        }

        // --- literal GRU (gi from dual fp32 sources [lx0 | l2lm], K=256) ---
        mma_gemm<0, 0, 0, 1, 1><<<gl3, 256, SMEM_BYTES>>>(nbp, nbp, lx0, l2lm, Wh_[8], Wl_[8], lgru_bih,
                                                          gi, nbw, nbw, 384, 0, L, 384, 256);
        mma_gemm<0, 0, 0, 0, 0><<<gl3, 256, SMEM_BYTES>>>(lch, lcl, nfp, nfp, Wh_[9], Wl_[9], lgru_bhh,
                                                          gh, nbw, nbw, 384, 0, L, 384, 128);
        {
            long long tot = (long long)L * 32;
            gru_pointwise2<<<(int)((tot + 255) / 256), 256>>>(gi, gh, lcur, lnext, lch, lcl, L);
        }
    }
}